// round 7
// baseline (speedup 1.0000x reference)
#include <cuda_runtime.h>

#define THREADS 256
#define ROWS    64
#define KQ      16          // k per thread (4 quarters)

// Prep block layout (floats) — identical in gPrep and shared memory:
#define OFF_WT   0        // 64 x 64  Wt[k][i]
#define OFF_GT   4096     // 64 x 64  Gt[k][i]
#define OFF_M    8192     // 64 x 64  M[k][l]
#define OFF_B    12288
#define OFF_WY   12352
#define OFF_wy   12416
#define OFF_wlt  12480
#define OFF_wys  12544
#define OFF_MISC 12608    // [0]=wl[64]
#define PREP_FLOATS 12624

// shared-only extras
#define OFF_RED  12624    // 8 warps x 2
#define OFF_PART 12640    // 3 partners x 3 values x 64 rows = 576
#define OFF_FLAG 13216
#define OFF_X    13220    // input stage, 64 rows x 65 (lives whole kernel)
#define OFF_S    17380    // s values,    64 rows x 65 (stride 65, conflict-free)
#define SMEM_FLOATS 21540
#define SMEM_BYTES  (SMEM_FLOATS * 4)

// ---- persistent device scratch ----
__device__ float        gPrep[PREP_FLOATS];
__device__ float        gPartI[512];
__device__ float        gPartN[512];
__device__ unsigned int gCount = 0;

__device__ __forceinline__ int pair_off(int i) {
    return 129 + i * (2 * 129 - i - 1) / 2;
}
__device__ __forceinline__ unsigned long long packpair(float a, float b) {
    unsigned long long r;
    asm("mov.b64 %0, {%1, %2};" : "=l"(r) : "f"(a), "f"(b));
    return r;
}
__device__ __forceinline__ void unpack2(unsigned long long v, float& a, float& b) {
    asm("mov.b64 {%0, %1}, %2;" : "=f"(a), "=f"(b) : "l"(v));
}
#define FMA2(acc, a, b) asm("fma.rn.f32x2 %0, %1, %2, %0;" : "+l"(acc) : "l"(a), "l"(b))

__device__ __forceinline__ float tanh_fast(float w) {
    float e, r;
    asm("ex2.approx.f32 %0, %1;" : "=f"(e) : "f"(w * 2.885390081777927f));
    asm("rcp.approx.f32 %0, %1;" : "=f"(r) : "f"(e + 1.0f));
    return fmaf(-2.0f, r, 1.0f);
}

// ---------------------------------------------------------------------------
__global__ void prep_kernel(const float* __restrict__ tw,
                            const float* __restrict__ tb,
                            const float* __restrict__ mw) {
    int tid = blockIdx.x * blockDim.x + threadIdx.x;
    if (tid >= PREP_FLOATS) return;
    float v = 0.0f;
    if (tid < 4096) {                       // Wt[k][i]
        int k = tid >> 6, i = tid & 63;
        v = tw[k * 65 + i];
    } else if (tid < 8192) {                // Gt[k][i]
        int idx = tid - 4096;
        int k = idx >> 6, i = idx & 63;
        v = mw[pair_off(i) + 64 + k - i];
    } else if (tid < 12288) {               // M[k][l]
        int idx = tid - 8192;
        int k = idx >> 6, l = idx & 63;
        if (k != l) {
            int a = k < l ? k : l;
            int b = k < l ? l : k;
            v = 0.5f * mw[pair_off(65 + a) + b - a - 1];
        }
    } else if (tid < 12352) {
        v = tb[tid - 12288];
    } else if (tid < 12416) {
        int k = tid - 12352;
        v = tw[k * 65 + 64];
    } else if (tid < 12480) {
        int i = tid - 12416;
        v = mw[pair_off(i) + 63 - i];
    } else if (tid < 12544) {
        v = mw[65 + (tid - 12480)];
    } else if (tid < 12608) {
        v = mw[pair_off(64) + (tid - 12544)];
    } else if (tid == 12608) {
        v = mw[64];
    }
    gPrep[tid] = v;
    if (tid == 0) gCount = 0;
}

// ---------------------------------------------------------------------------
__global__ void __launch_bounds__(THREADS, 2)
fused_kernel(const float* __restrict__ inps,
             float* __restrict__ out,
             int Bn) {
    extern __shared__ float sm[];
    const int t    = threadIdx.x;
    const int r    = t & 63;          // row 0..63
    const int q    = t >> 6;          // k-quarter (uniform per warp)
    const int kb   = q * KQ;
    const int row0 = blockIdx.x * ROWS;

    // coalesced weight copy
    {
        const float4* src = reinterpret_cast<const float4*>(gPrep);
        float4* dst = reinterpret_cast<float4*>(sm);
        for (int idx = t; idx < PREP_FLOATS / 4; idx += THREADS)
            dst[idx] = src[idx];
    }
    // coalesced input stage (stays valid the whole kernel)
    {
        const float4* src = reinterpret_cast<const float4*>(inps + (long)row0 * 65);
        float4* dst = reinterpret_cast<float4*>(sm + OFF_X);
        for (int idx = t; idx < (ROWS * 65) / 4; idx += THREADS)
            dst[idx] = src[idx];
    }
    __syncthreads();

    const float* myX = sm + OFF_X + r * 65;   // lane-stride 65 -> conflict-free
    float* myS = sm + OFF_S + r * 65;
    const float yv = myX[64];

    float accXW = 0.0f;
    if (q == 0) {
#pragma unroll 8
        for (int i = 0; i < 64; i++)
            accXW = fmaf(myX[i], sm[OFF_wy + i], accXW);
    }

    // ---------------- c passes: c_k = x . Wt[k][:] ----------------
    unsigned long long cacc[KQ];
#pragma unroll
    for (int kk = 0; kk < KQ; kk++) cacc[kk] = 0ULL;
#pragma unroll
    for (int half = 0; half < 2; half++) {
        unsigned long long xh[16];
#pragma unroll
        for (int j = 0; j < 16; j++)
            xh[j] = packpair(myX[32 * half + 2 * j], myX[32 * half + 2 * j + 1]);
#pragma unroll
        for (int kk = 0; kk < KQ; kk++) {
            const ulonglong2* wA =
                reinterpret_cast<const ulonglong2*>(sm + OFF_WT + (kb + kk) * 64 + 32 * half);
#pragma unroll
            for (int jj = 0; jj < 8; jj++) {
                ulonglong2 A = wA[jj];
                FMA2(cacc[kk], xh[2 * jj],     A.x);
                FMA2(cacc[kk], xh[2 * jj + 1], A.y);
            }
        }
    }

    // ---------------- epilogue: tanh, d/s, penalties ----------------
    float d[KQ];
    float accDW = 0.0f, accSW = 0.0f, accI = 0.0f, accN = 0.0f;
#pragma unroll
    for (int kk = 0; kk < KQ; kk++) {
        int k = kb + kk;
        float ca, cb;
        unpack2(cacc[kk], ca, cb);
        float cv = ca + cb + sm[OFF_B + k];
        float hv = yv * sm[OFF_WY + k];
        float w1 = cv + hv;
        float w2 = cv - hv;
        float t1 = tanh_fast(w1);
        float t2 = tanh_fast(w2);
        float dk = t1 - t2;
        float sk = t1 + t2;
        d[kk]   = dk;
        myS[k]  = sk;
        accDW = fmaf(dk, sm[OFF_wlt + k], accDW);
        accSW = fmaf(sk, sm[OFF_wys + k], accSW);
        float e1 = fmaf(-t1, t1, 1.0f);
        float e2 = fmaf(-t2, t2, 1.0f);
        accI = fmaf(e1, e1, accI);
        accI = fmaf(e2, e2, accI);
        float nt = fmaf(t2, w2, -(t1 * w1));
        accN = fmaf(nt, nt, accN);
    }

    // ---------------- a passes: a_k = x . Gt[k][:], gz1 = d.a ----------------
    unsigned long long aacc[KQ];
#pragma unroll
    for (int kk = 0; kk < KQ; kk++) aacc[kk] = 0ULL;
#pragma unroll
    for (int half = 0; half < 2; half++) {
        unsigned long long xh[16];
#pragma unroll
        for (int j = 0; j < 16; j++)
            xh[j] = packpair(myX[32 * half + 2 * j], myX[32 * half + 2 * j + 1]);
#pragma unroll
        for (int kk = 0; kk < KQ; kk++) {
            const ulonglong2* wG =
                reinterpret_cast<const ulonglong2*>(sm + OFF_GT + (kb + kk) * 64 + 32 * half);
#pragma unroll
            for (int jj = 0; jj < 8; jj++) {
                ulonglong2 A = wG[jj];
                FMA2(aacc[kk], xh[2 * jj],     A.x);
                FMA2(aacc[kk], xh[2 * jj + 1], A.y);
            }
        }
    }
    float gz = 0.0f;
#pragma unroll
    for (int kk = 0; kk < KQ; kk++) {
        float aa, ab;
        unpack2(aacc[kk], aa, ab);
        gz = fmaf(d[kk], aa + ab, gz);
    }

    __syncthreads();   // all s written

    // ---------------- Phase B: gz += sum_k d_k (M s)_k ----------------
    unsigned long long macc[KQ];
#pragma unroll
    for (int kk = 0; kk < KQ; kk++) macc[kk] = 0ULL;
#pragma unroll
    for (int half = 0; half < 2; half++) {
        unsigned long long sh[16];
#pragma unroll
        for (int j = 0; j < 16; j++)
            sh[j] = packpair(myS[32 * half + 2 * j], myS[32 * half + 2 * j + 1]);
#pragma unroll
        for (int kk = 0; kk < KQ; kk++) {
            const ulonglong2* wM =
                reinterpret_cast<const ulonglong2*>(sm + OFF_M + (kb + kk) * 64 + 32 * half);
#pragma unroll
            for (int jj = 0; jj < 8; jj++) {
                ulonglong2 A = wM[jj];
                FMA2(macc[kk], sh[2 * jj],     A.x);
                FMA2(macc[kk], sh[2 * jj + 1], A.y);
            }
        }
    }
#pragma unroll
    for (int kk = 0; kk < KQ; kk++) {
        float ma, mb;
        unpack2(macc[kk], ma, mb);
        gz = fmaf(d[kk], ma + mb, gz);
    }

    // ---------------- combine the 4 quarter threads ----------------
    if (q != 0) {
        int p = (q - 1) * 192;
        sm[OFF_PART + p + r]       = gz;
        sm[OFF_PART + p + 64 + r]  = accDW;
        sm[OFF_PART + p + 128 + r] = accSW;
    }
    __syncthreads();
    if (q == 0) {
        float gzT = gz, dwT = accDW, swT = accSW;
#pragma unroll
        for (int p = 0; p < 3; p++) {
            gzT += sm[OFF_PART + p * 192 + r];
            dwT += sm[OFF_PART + p * 192 + 64 + r];
            swT += sm[OFF_PART + p * 192 + 128 + r];
        }
        float diff = 1.0f
                   + 2.0f * yv * sm[OFF_MISC]
                   + dwT
                   + 2.0f * yv * accXW
                   + yv * swT
                   + gzT;
        out[row0 + r] = diff;
    }

    // ---------------- penalty reduction ----------------
#pragma unroll
    for (int off = 16; off > 0; off >>= 1) {
        accI += __shfl_xor_sync(0xffffffffu, accI, off);
        accN += __shfl_xor_sync(0xffffffffu, accN, off);
    }
    if ((t & 31) == 0) {
        sm[OFF_RED + (t >> 5)]     = accI;
        sm[OFF_RED + 8 + (t >> 5)] = accN;
    }
    __syncthreads();
    if (t == 0) {
        float pI = 0.0f, pN = 0.0f;
#pragma unroll
        for (int w = 0; w < 8; w++) { pI += sm[OFF_RED + w]; pN += sm[OFF_RED + 8 + w]; }
        gPartI[blockIdx.x] = pI;
        gPartN[blockIdx.x] = pN;
        __threadfence();
        unsigned int tk = atomicAdd(&gCount, 1u);
        sm[OFF_FLAG] = (tk == gridDim.x - 1) ? 1.0f : 0.0f;
    }
    __syncthreads();

    if (sm[OFF_FLAG] != 0.0f && t < 32) {
        __threadfence();
        double sI = 0.0, sN = 0.0;
        for (int i = t; i < (int)gridDim.x; i += 32) {
            sI += (double)gPartI[i];
            sN += (double)gPartN[i];
        }
#pragma unroll
        for (int off = 16; off > 0; off >>= 1) {
            sI += __shfl_xor_sync(0xffffffffu, sI, off);
            sN += __shfl_xor_sync(0xffffffffu, sN, off);
        }
        if (t == 0) {
            out[Bn]     = (float)(sI * (1.0 / 300.0));
            out[Bn + 1] = (float)sN;
            gCount = 0;   // reset for next graph replay
        }
    }
}

extern "C" void kernel_launch(void* const* d_in, const int* in_sizes, int n_in,
                              void* d_out, int out_size) {
    const float* inps = (const float*)d_in[0];
    const float* tw   = (const float*)d_in[1];
    const float* tb   = (const float*)d_in[2];
    const float* mw   = (const float*)d_in[3];
    float* out = (float*)d_out;

    int Bn = in_sizes[0] / 65;

    cudaFuncSetAttribute(fused_kernel,
                         cudaFuncAttributeMaxDynamicSharedMemorySize, SMEM_BYTES);

    prep_kernel<<<(PREP_FLOATS + 255) / 256, 256>>>(tw, tb, mw);
    fused_kernel<<<Bn / ROWS, THREADS, SMEM_BYTES>>>(inps, out, Bn);
}

// round 8
// speedup vs baseline: 1.1675x; 1.1675x over previous
#include <cuda_runtime.h>

#define THREADS 128
#define ROWS    64

// Prep block layout (floats) — identical in gPrep and shared memory:
#define OFF_WT   0        // 64 x 64  Wt[k][i]
#define OFF_GT   4096     // 64 x 64  Gt[k][i]
#define OFF_M    8192     // 64 x 64  M[k][l]
#define OFF_B    12288
#define OFF_WY   12352
#define OFF_wy   12416
#define OFF_wlt  12480
#define OFF_wys  12544
#define OFF_MISC 12608    // [0]=wl[64]
#define PREP_FLOATS 12624

// shared-only extras
#define OFF_RED  12624    // 4 warps x 2
#define OFF_PART 12632    // 3 partner warps x 3 vals x 64 rows = 576
#define OFF_FLAG 13208
#define OFF_X    13212    // input stage, 64 x 65
#define OFF_S    17372    // s values,    64 x 65 (stride 65, conflict-free)
#define SMEM_FLOATS 21532
#define SMEM_BYTES  (SMEM_FLOATS * 4)

// ---- persistent device scratch ----
__device__ float        gPrep[PREP_FLOATS];
__device__ float        gPartI[512];
__device__ float        gPartN[512];
__device__ unsigned int gCount = 0;

__device__ __forceinline__ int pair_off(int i) {
    return 129 + i * (2 * 129 - i - 1) / 2;
}
__device__ __forceinline__ unsigned long long packpair(float a, float b) {
    unsigned long long r;
    asm("mov.b64 %0, {%1, %2};" : "=l"(r) : "f"(a), "f"(b));
    return r;
}
__device__ __forceinline__ void unpack2(unsigned long long v, float& a, float& b) {
    asm("mov.b64 {%0, %1}, %2;" : "=f"(a), "=f"(b) : "l"(v));
}
#define FMA2(acc, a, b) asm("fma.rn.f32x2 %0, %1, %2, %0;" : "+l"(acc) : "l"(a), "l"(b))

__device__ __forceinline__ float tanh_fast(float w) {
    float e, r;
    asm("ex2.approx.f32 %0, %1;" : "=f"(e) : "f"(w * 2.885390081777927f));
    asm("rcp.approx.f32 %0, %1;" : "=f"(r) : "f"(e + 1.0f));
    return fmaf(-2.0f, r, 1.0f);
}

// ---------------------------------------------------------------------------
__global__ void prep_kernel(const float* __restrict__ tw,
                            const float* __restrict__ tb,
                            const float* __restrict__ mw) {
    int tid = blockIdx.x * blockDim.x + threadIdx.x;
    if (tid >= PREP_FLOATS) return;
    float v = 0.0f;
    if (tid < 4096) {                       // Wt[k][i]
        int k = tid >> 6, i = tid & 63;
        v = tw[k * 65 + i];
    } else if (tid < 8192) {                // Gt[k][i]
        int idx = tid - 4096;
        int k = idx >> 6, i = idx & 63;
        v = mw[pair_off(i) + 64 + k - i];
    } else if (tid < 12288) {               // M[k][l]
        int idx = tid - 8192;
        int k = idx >> 6, l = idx & 63;
        if (k != l) {
            int a = k < l ? k : l;
            int b = k < l ? l : k;
            v = 0.5f * mw[pair_off(65 + a) + b - a - 1];
        }
    } else if (tid < 12352) {
        v = tb[tid - 12288];
    } else if (tid < 12416) {
        int k = tid - 12352;
        v = tw[k * 65 + 64];
    } else if (tid < 12480) {
        int i = tid - 12416;
        v = mw[pair_off(i) + 63 - i];
    } else if (tid < 12544) {
        v = mw[65 + (tid - 12480)];
    } else if (tid < 12608) {
        v = mw[pair_off(64) + (tid - 12544)];
    } else if (tid == 12608) {
        v = mw[64];
    }
    gPrep[tid] = v;
    if (tid == 0) gCount = 0;
}

// ---------------------------------------------------------------------------
// 128 threads: warp = k-quarter (16 k's, warp-uniform weight reads),
// lane = row-pair (rows lane and lane+32). Each weight load feeds 2 rows.
// ---------------------------------------------------------------------------
__global__ void __launch_bounds__(THREADS, 2)
fused_kernel(const float* __restrict__ inps,
             float* __restrict__ out,
             int Bn) {
    extern __shared__ float sm[];
    const int t    = threadIdx.x;
    const int lane = t & 31;
    const int q    = t >> 5;          // warp index = k-quarter
    const int kb   = q * 16;
    const int rA   = lane;
    const int rB   = lane + 32;
    const int row0 = blockIdx.x * ROWS;

    // coalesced weight copy
    {
        const float4* src = reinterpret_cast<const float4*>(gPrep);
        float4* dst = reinterpret_cast<float4*>(sm);
        for (int idx = t; idx < PREP_FLOATS / 4; idx += THREADS)
            dst[idx] = src[idx];
    }
    // coalesced input stage
    {
        const float4* src = reinterpret_cast<const float4*>(inps + (long)row0 * 65);
        float4* dst = reinterpret_cast<float4*>(sm + OFF_X);
        for (int idx = t; idx < (ROWS * 65) / 4; idx += THREADS)
            dst[idx] = src[idx];
    }
    __syncthreads();

    const float* XA = sm + OFF_X + rA * 65;   // stride 65 -> conflict-free
    const float* XB = sm + OFF_X + rB * 65;
    float* SA = sm + OFF_S + rA * 65;
    float* SB = sm + OFF_S + rB * 65;
    const float yA = XA[64];
    const float yB = XB[64];

    float accXW_A = 0.0f, accXW_B = 0.0f;
    if (q == 0) {
#pragma unroll 8
        for (int i = 0; i < 64; i++) {
            float w = sm[OFF_wy + i];
            accXW_A = fmaf(XA[i], w, accXW_A);
            accXW_B = fmaf(XB[i], w, accXW_B);
        }
    }

    float dA[16], dB[16];
    float dwA = 0.0f, dwB = 0.0f, swA = 0.0f, swB = 0.0f;
    float gzA = 0.0f, gzB = 0.0f, accI = 0.0f, accN = 0.0f;

    // ================= Phase 1: c & a matvecs + tanh epilogue =================
#pragma unroll
    for (int ks = 0; ks < 2; ks++) {
        unsigned long long cA[8], cB[8], aA[8], aB[8];
#pragma unroll
        for (int kk = 0; kk < 8; kk++) { cA[kk] = 0ULL; cB[kk] = 0ULL; aA[kk] = 0ULL; aB[kk] = 0ULL; }

#pragma unroll
        for (int half = 0; half < 2; half++) {
            unsigned long long xAh[16], xBh[16];
#pragma unroll
            for (int j = 0; j < 16; j++) {
                xAh[j] = packpair(XA[32 * half + 2 * j], XA[32 * half + 2 * j + 1]);
                xBh[j] = packpair(XB[32 * half + 2 * j], XB[32 * half + 2 * j + 1]);
            }
#pragma unroll
            for (int kk = 0; kk < 8; kk++) {
                int k = kb + ks * 8 + kk;
                const ulonglong2* pW = reinterpret_cast<const ulonglong2*>(sm + OFF_WT + k * 64 + 32 * half);
                const ulonglong2* pG = reinterpret_cast<const ulonglong2*>(sm + OFF_GT + k * 64 + 32 * half);
#pragma unroll
                for (int jj = 0; jj < 8; jj++) {
                    ulonglong2 W = pW[jj];
                    ulonglong2 G = pG[jj];
                    int xi = 2 * jj;
                    FMA2(cA[kk], xAh[xi],     W.x);
                    FMA2(cA[kk], xAh[xi + 1], W.y);
                    FMA2(cB[kk], xBh[xi],     W.x);
                    FMA2(cB[kk], xBh[xi + 1], W.y);
                    FMA2(aA[kk], xAh[xi],     G.x);
                    FMA2(aA[kk], xAh[xi + 1], G.y);
                    FMA2(aB[kk], xBh[xi],     G.x);
                    FMA2(aB[kk], xBh[xi + 1], G.y);
                }
            }
        }

        // epilogue for these 8 k's
#pragma unroll
        for (int kk = 0; kk < 8; kk++) {
            int k  = kb + ks * 8 + kk;
            int kd = ks * 8 + kk;
            float bk  = sm[OFF_B + k];
            float wyk = sm[OFF_WY + k];
            float wlt = sm[OFF_wlt + k];
            float wys = sm[OFF_wys + k];

            float lo, hi;
            unpack2(cA[kk], lo, hi);
            float cvA = lo + hi + bk;
            unpack2(aA[kk], lo, hi);
            float avA = lo + hi;
            float hvA = yA * wyk;
            float w1 = cvA + hvA, w2 = cvA - hvA;
            float t1 = tanh_fast(w1), t2 = tanh_fast(w2);
            float dk = t1 - t2, sk = t1 + t2;
            dA[kd] = dk;
            SA[k]  = sk;
            gzA = fmaf(dk, avA, gzA);
            dwA = fmaf(dk, wlt, dwA);
            swA = fmaf(sk, wys, swA);
            float e1 = fmaf(-t1, t1, 1.0f), e2 = fmaf(-t2, t2, 1.0f);
            accI = fmaf(e1, e1, accI);
            accI = fmaf(e2, e2, accI);
            float nt = fmaf(t2, w2, -(t1 * w1));
            accN = fmaf(nt, nt, accN);

            unpack2(cB[kk], lo, hi);
            float cvB = lo + hi + bk;
            unpack2(aB[kk], lo, hi);
            float avB = lo + hi;
            float hvB = yB * wyk;
            w1 = cvB + hvB; w2 = cvB - hvB;
            t1 = tanh_fast(w1); t2 = tanh_fast(w2);
            dk = t1 - t2; sk = t1 + t2;
            dB[kd] = dk;
            SB[k]  = sk;
            gzB = fmaf(dk, avB, gzB);
            dwB = fmaf(dk, wlt, dwB);
            swB = fmaf(sk, wys, swB);
            e1 = fmaf(-t1, t1, 1.0f); e2 = fmaf(-t2, t2, 1.0f);
            accI = fmaf(e1, e1, accI);
            accI = fmaf(e2, e2, accI);
            nt = fmaf(t2, w2, -(t1 * w1));
            accN = fmaf(nt, nt, accN);
        }
    }

    __syncthreads();   // all s written

    // ================= Phase 2: gz += d^T M s =================
#pragma unroll
    for (int ks = 0; ks < 2; ks++) {
        unsigned long long mA[8], mB[8];
#pragma unroll
        for (int kk = 0; kk < 8; kk++) { mA[kk] = 0ULL; mB[kk] = 0ULL; }

#pragma unroll
        for (int half = 0; half < 2; half++) {
            unsigned long long sAh[16], sBh[16];
#pragma unroll
            for (int j = 0; j < 16; j++) {
                sAh[j] = packpair(SA[32 * half + 2 * j], SA[32 * half + 2 * j + 1]);
                sBh[j] = packpair(SB[32 * half + 2 * j], SB[32 * half + 2 * j + 1]);
            }
#pragma unroll
            for (int kk = 0; kk < 8; kk++) {
                int k = kb + ks * 8 + kk;
                const ulonglong2* pM = reinterpret_cast<const ulonglong2*>(sm + OFF_M + k * 64 + 32 * half);
#pragma unroll
                for (int jj = 0; jj < 8; jj++) {
                    ulonglong2 M = pM[jj];
                    int xi = 2 * jj;
                    FMA2(mA[kk], sAh[xi],     M.x);
                    FMA2(mA[kk], sAh[xi + 1], M.y);
                    FMA2(mB[kk], sBh[xi],     M.x);
                    FMA2(mB[kk], sBh[xi + 1], M.y);
                }
            }
        }
#pragma unroll
        for (int kk = 0; kk < 8; kk++) {
            int kd = ks * 8 + kk;
            float lo, hi;
            unpack2(mA[kk], lo, hi);
            gzA = fmaf(dA[kd], lo + hi, gzA);
            unpack2(mB[kk], lo, hi);
            gzB = fmaf(dB[kd], lo + hi, gzB);
        }
    }

    // ================= combine the 4 k-quarter warps =================
    if (q != 0) {
        int p = OFF_PART + (q - 1) * 192;
        sm[p + rA]       = gzA;  sm[p + rB]       = gzB;
        sm[p + 64 + rA]  = dwA;  sm[p + 64 + rB]  = dwB;
        sm[p + 128 + rA] = swA;  sm[p + 128 + rB] = swB;
    }
    __syncthreads();
    if (q == 0) {
#pragma unroll
        for (int p = 0; p < 3; p++) {
            int b = OFF_PART + p * 192;
            gzA += sm[b + rA];       gzB += sm[b + rB];
            dwA += sm[b + 64 + rA];  dwB += sm[b + 64 + rB];
            swA += sm[b + 128 + rA]; swB += sm[b + 128 + rB];
        }
        float wl64 = sm[OFF_MISC];
        out[row0 + rA] = 1.0f + 2.0f * yA * wl64 + dwA + 2.0f * yA * accXW_A + yA * swA + gzA;
        out[row0 + rB] = 1.0f + 2.0f * yB * wl64 + dwB + 2.0f * yB * accXW_B + yB * swB + gzB;
    }

    // ================= penalty reduction =================
#pragma unroll
    for (int off = 16; off > 0; off >>= 1) {
        accI += __shfl_xor_sync(0xffffffffu, accI, off);
        accN += __shfl_xor_sync(0xffffffffu, accN, off);
    }
    if (lane == 0) {
        sm[OFF_RED + q]     = accI;
        sm[OFF_RED + 4 + q] = accN;
    }
    __syncthreads();
    if (t == 0) {
        float pI = 0.0f, pN = 0.0f;
#pragma unroll
        for (int w = 0; w < 4; w++) { pI += sm[OFF_RED + w]; pN += sm[OFF_RED + 4 + w]; }
        gPartI[blockIdx.x] = pI;
        gPartN[blockIdx.x] = pN;
        __threadfence();
        unsigned int tk = atomicAdd(&gCount, 1u);
        sm[OFF_FLAG] = (tk == gridDim.x - 1) ? 1.0f : 0.0f;
    }
    __syncthreads();

    if (sm[OFF_FLAG] != 0.0f && t < 32) {
        __threadfence();
        double sI = 0.0, sN = 0.0;
        for (int i = t; i < (int)gridDim.x; i += 32) {
            sI += (double)gPartI[i];
            sN += (double)gPartN[i];
        }
#pragma unroll
        for (int off = 16; off > 0; off >>= 1) {
            sI += __shfl_xor_sync(0xffffffffu, sI, off);
            sN += __shfl_xor_sync(0xffffffffu, sN, off);
        }
        if (t == 0) {
            out[Bn]     = (float)(sI * (1.0 / 300.0));
            out[Bn + 1] = (float)sN;
            gCount = 0;   // reset for next graph replay
        }
    }
}

extern "C" void kernel_launch(void* const* d_in, const int* in_sizes, int n_in,
                              void* d_out, int out_size) {
    const float* inps = (const float*)d_in[0];
    const float* tw   = (const float*)d_in[1];
    const float* tb   = (const float*)d_in[2];
    const float* mw   = (const float*)d_in[3];
    float* out = (float*)d_out;

    int Bn = in_sizes[0] / 65;

    cudaFuncSetAttribute(fused_kernel,
                         cudaFuncAttributeMaxDynamicSharedMemorySize, SMEM_BYTES);

    prep_kernel<<<(PREP_FLOATS + 255) / 256, 256>>>(tw, tb, mw);
    fused_kernel<<<Bn / ROWS, THREADS, SMEM_BYTES>>>(inps, out, Bn);
}